// round 1
// baseline (speedup 1.0000x reference)
#include <cuda_runtime.h>

#define D_ 768
#define B_ 64
#define A_ 256
#define L_ 2
#define NG1 4
#define NG2 8

// Scratch: h1[g1][b][d] and h2[pair][b][d] (pair = g1*8+g2). 0.79 MB + 6.3 MB.
__device__ float g_h1[NG1 * B_ * D_];
__device__ float g_h2[NG1 * NG2 * B_ * D_];

// Packed f32x2 FMA (sm_100+): 2 FLOP-pairs per issue slot on the fma pipe.
__device__ __forceinline__ void ffma2(unsigned long long& acc,
                                      unsigned long long a,
                                      unsigned long long b) {
    asm("fma.rn.f32x2 %0, %1, %2, %0;" : "+l"(acc) : "l"(a), "l"(b));
}
__device__ __forceinline__ unsigned long long pack2(float lo, float hi) {
    unsigned long long r;
    asm("mov.b64 %0, {%1, %2};" : "=l"(r) : "f"(lo), "f"(hi));
    return r;
}

// C[64, 768] = A[64,768] @ W[768,768] + bias[768], one BN-wide N-stripe per block.
// 128 threads, BM=64, BK=16, TM=8 (packed as 4 m-pairs), TN = 2 or 4.
// Accumulators packed along M so the A operand comes straight out of LDS.64.
template <int TN>
__device__ __forceinline__ void gemm_tile(const float* __restrict__ A,
                                          const float* __restrict__ W,
                                          const float* __restrict__ bias,
                                          float* __restrict__ C,
                                          int n0) {
    constexpr int BN = TN * 16;
    constexpr int BK = 16;
    constexpr int TM = 8;

    __shared__ __align__(16) float As[BK][66];   // [k][m], pad 66 keeps 8B align + kills STS conflicts
    __shared__ __align__(16) float Ws[BK][BN];   // [k][n]

    const int t  = threadIdx.x;   // 0..127
    const int mg = t >> 4;        // 0..7  -> 8 m-rows each
    const int ng = t & 15;        // 0..15 -> TN n-cols each

    unsigned long long acc[TM / 2][TN];
#pragma unroll
    for (int i = 0; i < TM / 2; i++)
#pragma unroll
        for (int j = 0; j < TN; j++) acc[i][j] = 0ull;

    for (int k0 = 0; k0 < D_; k0 += BK) {
        // ---- load A tile (64 rows x 16 k) transposed into As[k][m] ----
#pragma unroll
        for (int i = 0; i < 2; i++) {
            int idx = t + i * 128;         // 0..255 float4s
            int row = idx >> 2;            // 0..63
            int kq  = (idx & 3) * 4;       // 0,4,8,12
            float4 v = *(const float4*)(A + row * D_ + k0 + kq);
            As[kq + 0][row] = v.x;
            As[kq + 1][row] = v.y;
            As[kq + 2][row] = v.z;
            As[kq + 3][row] = v.w;
        }
        // ---- load W tile (16 k x BN) ----
#pragma unroll
        for (int i = 0; i < (BK * BN / 4) / 128; i++) {
            int idx = t + i * 128;
            int kr  = idx / (BN / 4);
            int nc  = (idx % (BN / 4)) * 4;
            *(float4*)&Ws[kr][nc] = *(const float4*)(W + (k0 + kr) * D_ + n0 + nc);
        }
        __syncthreads();

#pragma unroll
        for (int kk = 0; kk < BK; kk++) {
            unsigned long long av[TM / 2];
#pragma unroll
            for (int i = 0; i < TM / 2; i++)
                av[i] = *(const unsigned long long*)&As[kk][mg * TM + i * 2];

            unsigned long long bv[TN];
            if constexpr (TN == 4) {
                float4 bq = *(const float4*)&Ws[kk][ng * 4];
                bv[0] = pack2(bq.x, bq.x);
                bv[1] = pack2(bq.y, bq.y);
                bv[2] = pack2(bq.z, bq.z);
                bv[3] = pack2(bq.w, bq.w);
            } else {
                float2 bq = *(const float2*)&Ws[kk][ng * 2];
                bv[0] = pack2(bq.x, bq.x);
                bv[1] = pack2(bq.y, bq.y);
            }
#pragma unroll
            for (int i = 0; i < TM / 2; i++)
#pragma unroll
                for (int j = 0; j < TN; j++) ffma2(acc[i][j], av[i], bv[j]);
        }
        __syncthreads();
    }

    // ---- epilogue: add bias, write C ----
#pragma unroll
    for (int j = 0; j < TN; j++) {
        int col = n0 + ng * TN + j;
        float bb = bias[col];
#pragma unroll
        for (int i = 0; i < TM / 2; i++) {
            float lo, hi;
            asm("mov.b64 {%0, %1}, %2;" : "=f"(lo), "=f"(hi) : "l"(acc[i][j]));
            int row = mg * TM + i * 2;
            C[row * D_ + col]       = lo + bb;
            C[(row + 1) * D_ + col] = hi + bb;
        }
    }
}

// Stage 1: h1[g] = pooled @ W1[g] + b1[g].  Grid (24 n-stripes, 4 groups) = 96 blocks.
__global__ void __launch_bounds__(128) stage1_kernel(const float* __restrict__ pooled,
                                                     const float* __restrict__ W1,
                                                     const float* __restrict__ b1) {
    int g = blockIdx.y;
    gemm_tile<2>(pooled, W1 + g * D_ * D_, b1 + g * D_, g_h1 + g * B_ * D_,
                 blockIdx.x * 32);
}

// Stage 2: h2[p] = h1[p>>3] @ W2[p&7] + b2[p&7].  Grid (12, 32) = 384 blocks.
__global__ void __launch_bounds__(128) stage2_kernel(const float* __restrict__ W2,
                                                     const float* __restrict__ b2) {
    int p  = blockIdx.y;
    int g1 = p >> 3;
    int g2 = p & 7;
    gemm_tile<4>(g_h1 + g1 * B_ * D_, W2 + g2 * D_ * D_, b2 + g2 * D_,
                 g_h2 + p * B_ * D_, blockIdx.x * 64);
}

// Stage 3: out[b][a][l] = h2[pair(a)][b][:] . Wh[a][:,l] + bh[a][l].
// One block per annotator; Wh[a] staged in smem; one warp per batch row.
__global__ void __launch_bounds__(256) heads_kernel(const float* __restrict__ Wh,
                                                    const float* __restrict__ bh,
                                                    const int* __restrict__ g1i,
                                                    const int* __restrict__ g2i,
                                                    float* __restrict__ out) {
    int a = blockIdx.x;
    __shared__ __align__(16) float wh[D_ * L_];
    for (int i = threadIdx.x; i < (D_ * L_) / 4; i += 256)
        *(float4*)&wh[i * 4] = *(const float4*)&Wh[a * D_ * L_ + i * 4];
    __syncthreads();

    int p = g1i[a] * NG2 + g2i[a];
    const float* h = g_h2 + p * B_ * D_;
    float bh0 = bh[a * L_ + 0];
    float bh1 = bh[a * L_ + 1];

    int warp = threadIdx.x >> 5;
    int lane = threadIdx.x & 31;

    for (int b = warp; b < B_; b += 8) {
        const float* hb = h + b * D_;
        float acc0 = 0.f, acc1 = 0.f;
#pragma unroll
        for (int i = 0; i < D_ / 128; i++) {
            int d = i * 128 + lane * 4;
            float4 v = *(const float4*)(hb + d);
            float2 w0 = *(const float2*)&wh[(d + 0) * 2];
            float2 w1 = *(const float2*)&wh[(d + 1) * 2];
            float2 w2 = *(const float2*)&wh[(d + 2) * 2];
            float2 w3 = *(const float2*)&wh[(d + 3) * 2];
            acc0 += v.x * w0.x + v.y * w1.x + v.z * w2.x + v.w * w3.x;
            acc1 += v.x * w0.y + v.y * w1.y + v.z * w2.y + v.w * w3.y;
        }
#pragma unroll
        for (int off = 16; off; off >>= 1) {
            acc0 += __shfl_down_sync(0xffffffffu, acc0, off);
            acc1 += __shfl_down_sync(0xffffffffu, acc1, off);
        }
        if (lane == 0) {
            out[(b * A_ + a) * L_ + 0] = acc0 + bh0;
            out[(b * A_ + a) * L_ + 1] = acc1 + bh1;
        }
    }
}

extern "C" void kernel_launch(void* const* d_in, const int* in_sizes, int n_in,
                              void* d_out, int out_size) {
    const float* pooled = (const float*)d_in[0];
    const float* W1     = (const float*)d_in[1];
    const float* b1     = (const float*)d_in[2];
    const float* W2     = (const float*)d_in[3];
    const float* b2     = (const float*)d_in[4];
    const float* Wh     = (const float*)d_in[5];
    const float* bh     = (const float*)d_in[6];
    const int*   g1i    = (const int*)d_in[7];
    const int*   g2i    = (const int*)d_in[8];
    float* out = (float*)d_out;

    stage1_kernel<<<dim3(D_ / 32, NG1), 128>>>(pooled, W1, b1);
    stage2_kernel<<<dim3(D_ / 64, NG1 * NG2), 128>>>(W2, b2);
    heads_kernel<<<A_, 256>>>(Wh, bh, g1i, g2i, out);
}